// round 11
// baseline (speedup 1.0000x reference)
#include <cuda_runtime.h>
#include <cuda_fp16.h>
#include <math.h>

#define NMAX 100000
#define EMAX 3200000
#define DIMF 128
#define SROW (DIMF + 8)   // padded smem row (halves)

// ---------------- scratch ----------------------------------------------------
__device__ __align__(16) unsigned g_q8[(size_t)NMAX * 32];   // int8 rows (biased u8), 32 words/row
__device__ __align__(16) float  g_qs[NMAX];                  // per-row dequant scale
__device__ __align__(16) __half g_b16[(size_t)NMAX * DIMF];  // agg1 out (GEMM2 in)
__device__ __align__(16) __half g_W1h[DIMF * DIMF];
__device__ __align__(16) __half g_W2h[DIMF * DIMF];
__device__ __align__(16) int    g_deg[NMAX];
__device__ __align__(16) float  g_dinv[NMAX];
__device__ __align__(16) int    g_rowptr[NMAX + 1];
__device__ __align__(16) int    g_bsums[512];
__device__ __align__(16) unsigned long long g_edge[EMAX];    // {ws_bits:32 | col:32}

// ---------------- mma / ldmatrix helpers --------------------------------------
__device__ __forceinline__ unsigned su32(const void* p) {
    return (unsigned)__cvta_generic_to_shared(p);
}
__device__ __forceinline__ void ldsm4(unsigned& r0, unsigned& r1, unsigned& r2,
                                      unsigned& r3, unsigned addr) {
    asm volatile("ldmatrix.sync.aligned.m8n8.x4.shared.b16 {%0,%1,%2,%3}, [%4];"
                 : "=r"(r0), "=r"(r1), "=r"(r2), "=r"(r3) : "r"(addr));
}
__device__ __forceinline__ void ldsm4t(unsigned& r0, unsigned& r1, unsigned& r2,
                                       unsigned& r3, unsigned addr) {
    asm volatile("ldmatrix.sync.aligned.m8n8.x4.trans.shared.b16 {%0,%1,%2,%3}, [%4];"
                 : "=r"(r0), "=r"(r1), "=r"(r2), "=r"(r3) : "r"(addr));
}
__device__ __forceinline__ void mma16816(float* d, unsigned a0, unsigned a1,
                                         unsigned a2, unsigned a3,
                                         unsigned b0, unsigned b1) {
    asm volatile("mma.sync.aligned.m16n8k16.row.col.f32.f16.f16.f32 "
                 "{%0,%1,%2,%3},{%4,%5,%6,%7},{%8,%9},{%0,%1,%2,%3};"
                 : "+f"(d[0]), "+f"(d[1]), "+f"(d[2]), "+f"(d[3])
                 : "r"(a0), "r"(a1), "r"(a2), "r"(a3), "r"(b0), "r"(b1));
}

// ---------------- CSR build ----------------------------------------------------
__global__ void k_zero_int(int* __restrict__ p, int n) {
    int i = blockIdx.x * blockDim.x + threadIdx.x;
    if (i < n) p[i] = 0;
}
__global__ void k_hist(const int* __restrict__ dst, int E, int* __restrict__ deg) {
    int e = blockIdx.x * blockDim.x + threadIdx.x;
    if (e < E) atomicAdd(&deg[dst[e]], 1);
}
__global__ void k_scan1(const int* __restrict__ in, int* __restrict__ out,
                        int* __restrict__ bsums, float* __restrict__ dinv, int n) {
    __shared__ int wsum[8];
    int tid  = threadIdx.x;
    int base = blockIdx.x * 1024 + tid * 4;
    int v0 = 0, v1 = 0, v2 = 0, v3 = 0;
    if (base + 0 < n) v0 = in[base + 0];
    if (base + 1 < n) v1 = in[base + 1];
    if (base + 2 < n) v2 = in[base + 2];
    if (base + 3 < n) v3 = in[base + 3];
    if (base + 0 < n) dinv[base + 0] = rsqrtf((float)(v0 + 1));
    if (base + 1 < n) dinv[base + 1] = rsqrtf((float)(v1 + 1));
    if (base + 2 < n) dinv[base + 2] = rsqrtf((float)(v2 + 1));
    if (base + 3 < n) dinv[base + 3] = rsqrtf((float)(v3 + 1));
    int s = v0 + v1 + v2 + v3;
    int lane = tid & 31, wid = tid >> 5;
    int inc = s;
    #pragma unroll
    for (int o = 1; o < 32; o <<= 1) {
        int t = __shfl_up_sync(0xffffffffu, inc, o);
        if (lane >= o) inc += t;
    }
    if (lane == 31) wsum[wid] = inc;
    __syncthreads();
    if (tid == 0) {
        int run = 0;
        #pragma unroll
        for (int i = 0; i < 8; i++) { int t = wsum[i]; wsum[i] = run; run += t; }
        bsums[blockIdx.x] = run;
    }
    __syncthreads();
    int ex = wsum[wid] + inc - s;
    if (base + 0 < n) out[base + 0] = ex;
    if (base + 1 < n) out[base + 1] = ex + v0;
    if (base + 2 < n) out[base + 2] = ex + v0 + v1;
    if (base + 3 < n) out[base + 3] = ex + v0 + v1 + v2;
}
__global__ void k_scan2(int* __restrict__ bsums, int nb) {
    __shared__ int wsum[4];
    int tid = threadIdx.x;
    int v = (tid < nb) ? bsums[tid] : 0;
    int lane = tid & 31, wid = tid >> 5;
    int inc = v;
    #pragma unroll
    for (int o = 1; o < 32; o <<= 1) {
        int t = __shfl_up_sync(0xffffffffu, inc, o);
        if (lane >= o) inc += t;
    }
    if (lane == 31) wsum[wid] = inc;
    __syncthreads();
    if (tid == 0) {
        int run = 0;
        #pragma unroll
        for (int i = 0; i < 4; i++) { int t = wsum[i]; wsum[i] = run; run += t; }
    }
    __syncthreads();
    if (tid < nb) bsums[tid] = wsum[wid] + inc - v;
}
__global__ void k_scan3(int* __restrict__ rowptr, const int* __restrict__ bsums,
                        int* __restrict__ fill, int n, int E) {
    int i = blockIdx.x * 1024 + threadIdx.x;
    if (i < n) { rowptr[i] += bsums[blockIdx.x]; fill[i] = 0; }
    if (i == 0) rowptr[n] = E;
}
__global__ void k_scatter(const int* __restrict__ srcp, const int* __restrict__ dstp,
                          int E, const int* __restrict__ rowptr, int* __restrict__ fill,
                          const float* __restrict__ dinv,
                          unsigned long long* __restrict__ edge) {
    int e = blockIdx.x * blockDim.x + threadIdx.x;
    if (e >= E) return;
    int s = srcp[e];
    int d = dstp[e];
    int pos = rowptr[d] + atomicAdd(&fill[d], 1);
    unsigned long long w = (unsigned long long)__float_as_uint(dinv[s]);
    edge[pos] = (w << 32) | (unsigned int)s;
}

// ---------------- weight convert ------------------------------------------------
__global__ void k_cvtW(const float* __restrict__ W1, const float* __restrict__ W2,
                       __half* __restrict__ W1h, __half* __restrict__ W2h) {
    int i = blockIdx.x * blockDim.x + threadIdx.x;
    if (i < DIMF * DIMF) {
        W1h[i] = __float2half(W1[i]);
        W2h[i] = __float2half(W2[i]);
    }
}

// ---------------- HMMA GEMM: quantized int8 output + per-row scale -------------
__device__ __forceinline__ void ldrows(__half (*As)[SROW], const float* X,
                                       int rowbase, int rows, int tid) {
    for (int i = tid; i < rows * 16; i += 256) {
        int r = i >> 4, c8 = (i & 15) * 8;
        const float4* p = (const float4*)(X + (size_t)(rowbase + r) * DIMF + c8);
        float4 f0 = p[0], f1 = p[1];
        __half2 h0 = __floats2half2_rn(f0.x, f0.y), h1 = __floats2half2_rn(f0.z, f0.w);
        __half2 h2 = __floats2half2_rn(f1.x, f1.y), h3 = __floats2half2_rn(f1.z, f1.w);
        uint4 u;
        u.x = *(unsigned*)&h0; u.y = *(unsigned*)&h1;
        u.z = *(unsigned*)&h2; u.w = *(unsigned*)&h3;
        *(uint4*)&As[r][c8] = u;
    }
}
__device__ __forceinline__ void ldrows(__half (*As)[SROW], const __half* X,
                                       int rowbase, int rows, int tid) {
    for (int i = tid; i < rows * 16; i += 256) {
        int r = i >> 4, c8 = (i & 15) * 8;
        *(uint4*)&As[r][c8] = *(const uint4*)(X + (size_t)(rowbase + r) * DIMF + c8);
    }
}

// quantize one row slice held by this thread: 16 nb-blocks x 2 cols
__device__ __forceinline__ void quant_store(float a0[16], float a1[16],
                                            unsigned char* __restrict__ q8b,
                                            float* __restrict__ qscale,
                                            int row, int lane, int ocol, bool valid) {
    float m = 0.f;
    #pragma unroll
    for (int nb = 0; nb < 16; nb++) {
        m = fmaxf(m, fabsf(a0[nb]));
        m = fmaxf(m, fabsf(a1[nb]));
    }
    m = fmaxf(m, __shfl_xor_sync(0xffffffffu, m, 1));
    m = fmaxf(m, __shfl_xor_sync(0xffffffffu, m, 2));
    float inv = (m > 0.f) ? 127.f / m : 0.f;
    if (!valid) return;
    if ((lane & 3) == 0) qscale[row] = m * (1.f / 127.f);
    unsigned char* base = q8b + (size_t)row * DIMF;
    #pragma unroll
    for (int nb = 0; nb < 16; nb++) {
        int q0 = __float2int_rn(a0[nb] * inv) + 128;
        int q1 = __float2int_rn(a1[nb] * inv) + 128;
        unsigned short us = (unsigned short)((q0 & 0xff) | ((q1 & 0xff) << 8));
        *(unsigned short*)(base + nb * 8 + ocol) = us;
    }
}

template <typename TIN>
__global__ void k_gemm_hmma(const TIN* __restrict__ X, const __half* __restrict__ Wh,
                            unsigned* __restrict__ q8, float* __restrict__ qscale,
                            int nrows) {
    extern __shared__ __half smemh[];
    __half (*As)[SROW] = (__half(*)[SROW])smemh;
    __half (*Bs)[SROW] = (__half(*)[SROW])(smemh + 128 * SROW);

    int tid = threadIdx.x;
    int rowbase = blockIdx.x * 128;
    int rows = nrows - rowbase; if (rows > 128) rows = 128;

    #pragma unroll 4
    for (int i = tid; i < 128 * 16; i += 256) {
        int r = i >> 4, c8 = (i & 15) * 8;
        *(uint4*)&Bs[r][c8] = *(const uint4*)(Wh + r * DIMF + c8);
    }
    ldrows(As, X, rowbase, rows, tid);
    __syncthreads();

    int warp = tid >> 5, lane = tid & 31;
    int m0 = warp * 16;
    float acc[16][4];
    #pragma unroll
    for (int i = 0; i < 16; i++)
        #pragma unroll
        for (int j = 0; j < 4; j++) acc[i][j] = 0.f;

    unsigned a_addr = su32(&As[m0 + (lane & 15)][(lane >> 4) * 8]);
    unsigned b_addr = su32(&Bs[lane & 15][(lane >> 4) * 8]);

    #pragma unroll
    for (int ks = 0; ks < 8; ks++) {
        unsigned a0, a1, a2, a3;
        ldsm4(a0, a1, a2, a3, a_addr + ks * 16 * 2);
        #pragma unroll
        for (int pr = 0; pr < 8; pr++) {
            unsigned b0, b1, b2, b3;
            ldsm4t(b0, b1, b2, b3, b_addr + ks * 16 * (SROW * 2) + pr * 16 * 2);
            mma16816(acc[2 * pr + 0], a0, a1, a2, a3, b0, b1);
            mma16816(acc[2 * pr + 1], a0, a1, a2, a3, b2, b3);
        }
    }

    int orow = lane >> 2, ocol = (lane & 3) * 2;
    int r0 = m0 + orow, r1 = r0 + 8;
    float v0[16], v1[16];
    #pragma unroll
    for (int nb = 0; nb < 16; nb++) { v0[nb] = acc[nb][0]; v1[nb] = acc[nb][1]; }
    quant_store(v0, v1, (unsigned char*)q8, qscale, rowbase + r0, lane, ocol, r0 < rows);
    #pragma unroll
    for (int nb = 0; nb < 16; nb++) { v0[nb] = acc[nb][2]; v1[nb] = acc[nb][3]; }
    quant_store(v0, v1, (unsigned char*)q8, qscale, rowbase + r1, lane, ocol, r1 < rows);
}

// ---------------- agg core: int8 gather + PRMT dequant, fp16->fp32 accum -------
__device__ __forceinline__ float4 agg_row_q8(const unsigned* __restrict__ q8,
                                             const float* __restrict__ qscale,
                                             const unsigned long long* __restrict__ edge,
                                             const float* __restrict__ dinv,
                                             const float* __restrict__ bias,
                                             int v, int e0, int e1, int lane) {
    unsigned cm = 0x64806480u;           // half2(1152, 1152): bias for 0x64|u8 trick
    __half2 h1152 = *(__half2*)&cm;
    __half2 hz = __floats2half2_rn(0.f, 0.f);

    float ax = 0.f, ay = 0.f, az = 0.f, aw = 0.f;
    int e = e0;
    for (; e + 8 <= e1; e += 8) {
        unsigned long long p[8];
        #pragma unroll
        for (int j = 0; j < 8; j++) p[j] = __ldg(edge + e + j);
        unsigned rv[8]; __half2 w2[8];
        #pragma unroll
        for (int j = 0; j < 8; j++) {
            int s = (int)(unsigned)p[j];
            rv[j] = __ldg(q8 + (size_t)s * 32 + lane);
            float wq = __uint_as_float((unsigned)(p[j] >> 32)) * __ldg(qscale + s);
            w2[j] = __float2half2_rn(wq);
        }
        __half2 h0 = hz, h1 = hz;
        #pragma unroll
        for (int j = 0; j < 8; j++) {
            unsigned lo = __byte_perm(rv[j], 0x64646464u, 0x4140);
            unsigned hi = __byte_perm(rv[j], 0x64646464u, 0x4342);
            __half2 q01 = __hsub2(*(__half2*)&lo, h1152);
            __half2 q23 = __hsub2(*(__half2*)&hi, h1152);
            h0 = __hfma2(w2[j], q01, h0);
            h1 = __hfma2(w2[j], q23, h1);
        }
        float2 f0 = __half22float2(h0), f1 = __half22float2(h1);
        ax += f0.x; ay += f0.y; az += f1.x; aw += f1.y;
    }
    if (e < e1) {
        __half2 h0 = hz, h1 = hz;
        for (; e < e1; e++) {
            unsigned long long p = __ldg(edge + e);
            int s = (int)(unsigned)p;
            unsigned rv = __ldg(q8 + (size_t)s * 32 + lane);
            float wq = __uint_as_float((unsigned)(p >> 32)) * __ldg(qscale + s);
            __half2 w2 = __float2half2_rn(wq);
            unsigned lo = __byte_perm(rv, 0x64646464u, 0x4140);
            unsigned hi = __byte_perm(rv, 0x64646464u, 0x4342);
            h0 = __hfma2(w2, __hsub2(*(__half2*)&lo, h1152), h0);
            h1 = __hfma2(w2, __hsub2(*(__half2*)&hi, h1152), h1);
        }
        float2 f0 = __half22float2(h0), f1 = __half22float2(h1);
        ax += f0.x; ay += f0.y; az += f1.x; aw += f1.y;
    }

    float dv = dinv[v];
    float qsv = __ldg(qscale + v);
    float sws = dv * dv * qsv;
    unsigned rvv = __ldg(q8 + (size_t)v * 32 + lane);
    unsigned lo = __byte_perm(rvv, 0x64646464u, 0x4140);
    unsigned hi = __byte_perm(rvv, 0x64646464u, 0x4342);
    float2 hs0 = __half22float2(__hsub2(*(__half2*)&lo, h1152));
    float2 hs1 = __half22float2(__hsub2(*(__half2*)&hi, h1152));
    float4 b = __ldg((const float4*)bias + lane);
    float4 o;
    o.x = fmaxf(fmaf(dv, ax, fmaf(sws, hs0.x, b.x)), 0.f);
    o.y = fmaxf(fmaf(dv, ay, fmaf(sws, hs0.y, b.y)), 0.f);
    o.z = fmaxf(fmaf(dv, az, fmaf(sws, hs1.x, b.z)), 0.f);
    o.w = fmaxf(fmaf(dv, aw, fmaf(sws, hs1.y, b.w)), 0.f);
    return o;
}

// layer-1 aggregation: fp16 out (GEMM2 input)
__global__ void k_agg(const unsigned* __restrict__ q8, const float* __restrict__ qscale,
                      const int* __restrict__ rowptr,
                      const unsigned long long* __restrict__ edge,
                      const float* __restrict__ dinv, const float* __restrict__ bias,
                      __half* __restrict__ out, int N) {
    int v = (blockIdx.x * blockDim.x + threadIdx.x) >> 5;
    int lane = threadIdx.x & 31;
    if (v >= N) return;
    int e0 = rowptr[v], e1 = rowptr[v + 1];
    float4 o = agg_row_q8(q8, qscale, edge, dinv, bias, v, e0, e1, lane);
    __half2 p0 = __floats2half2_rn(o.x, o.y);
    __half2 p1 = __floats2half2_rn(o.z, o.w);
    uint2 u;
    u.x = *(unsigned*)&p0; u.y = *(unsigned*)&p1;
    ((uint2*)(out + (size_t)v * DIMF))[lane] = u;
}

// layer-2 aggregation fused with FC(128->40) + log_softmax
__global__ void k_agg_fc(const unsigned* __restrict__ q8, const float* __restrict__ qscale,
                         const int* __restrict__ rowptr,
                         const unsigned long long* __restrict__ edge,
                         const float* __restrict__ dinv, const float* __restrict__ bias,
                         const float* __restrict__ Wfc, const float* __restrict__ bfc,
                         float* __restrict__ out, int N) {
    __shared__ __align__(16) float sh[8][DIMF];
    int w = threadIdx.x >> 5;
    int lane = threadIdx.x & 31;
    int v = blockIdx.x * 8 + w;
    if (v >= N) return;

    int e0 = rowptr[v], e1 = rowptr[v + 1];
    float4 o = agg_row_q8(q8, qscale, edge, dinv, bias, v, e0, e1, lane);
    ((float4*)&sh[w][0])[lane] = o;
    __syncwarp();

    float acc0 = 0.f, acc1 = 0.f;
    bool hi = (lane < 8);
    #pragma unroll 4
    for (int k4 = 0; k4 < 32; k4++) {
        float4 xv = ((const float4*)&sh[w][0])[k4];
        int k = k4 * 4;
        acc0 = fmaf(xv.x, __ldg(Wfc + (k + 0) * 40 + lane), acc0);
        acc0 = fmaf(xv.y, __ldg(Wfc + (k + 1) * 40 + lane), acc0);
        acc0 = fmaf(xv.z, __ldg(Wfc + (k + 2) * 40 + lane), acc0);
        acc0 = fmaf(xv.w, __ldg(Wfc + (k + 3) * 40 + lane), acc0);
        if (hi) {
            acc1 = fmaf(xv.x, __ldg(Wfc + (k + 0) * 40 + 32 + lane), acc1);
            acc1 = fmaf(xv.y, __ldg(Wfc + (k + 1) * 40 + 32 + lane), acc1);
            acc1 = fmaf(xv.z, __ldg(Wfc + (k + 2) * 40 + 32 + lane), acc1);
            acc1 = fmaf(xv.w, __ldg(Wfc + (k + 3) * 40 + 32 + lane), acc1);
        }
    }
    acc0 += __ldg(bfc + lane);
    if (hi) acc1 += __ldg(bfc + 32 + lane);

    float m = hi ? fmaxf(acc0, acc1) : acc0;
    #pragma unroll
    for (int o2 = 16; o2; o2 >>= 1) m = fmaxf(m, __shfl_xor_sync(0xffffffffu, m, o2));
    float s = expf(acc0 - m) + (hi ? expf(acc1 - m) : 0.f);
    #pragma unroll
    for (int o2 = 16; o2; o2 >>= 1) s += __shfl_xor_sync(0xffffffffu, s, o2);
    float lse = logf(s) + m;

    out[(size_t)v * 40 + lane] = acc0 - lse;
    if (hi) out[(size_t)v * 40 + 32 + lane] = acc1 - lse;
}

// ---------------- host launcher ----------------------------------------------
extern "C" void kernel_launch(void* const* d_in, const int* in_sizes, int n_in,
                              void* d_out, int out_size) {
    const float* x    = (const float*)d_in[0];
    const float* W1   = (const float*)d_in[1];
    const float* b1   = (const float*)d_in[2];
    const float* W2   = (const float*)d_in[3];
    const float* b2   = (const float*)d_in[4];
    const float* Wfc  = (const float*)d_in[5];
    const float* bfc  = (const float*)d_in[6];
    const int*   eidx = (const int*)d_in[7];
    float* out = (float*)d_out;

    int N = in_sizes[0] / DIMF;
    int E = in_sizes[7] / 2;
    if (N > NMAX) N = NMAX;
    if (E > EMAX) E = EMAX;

    unsigned* pq8;
    __half *pb16, *pW1h, *pW2h;
    float *pdinv, *pqs;
    int *pdeg, *prow, *pbs;
    unsigned long long* pedge;
    cudaGetSymbolAddress((void**)&pq8,   g_q8);
    cudaGetSymbolAddress((void**)&pqs,   g_qs);
    cudaGetSymbolAddress((void**)&pb16,  g_b16);
    cudaGetSymbolAddress((void**)&pW1h,  g_W1h);
    cudaGetSymbolAddress((void**)&pW2h,  g_W2h);
    cudaGetSymbolAddress((void**)&pdeg,  g_deg);
    cudaGetSymbolAddress((void**)&pdinv, g_dinv);
    cudaGetSymbolAddress((void**)&prow,  g_rowptr);
    cudaGetSymbolAddress((void**)&pbs,   g_bsums);
    cudaGetSymbolAddress((void**)&pedge, g_edge);

    int smem_gemm = 2 * 128 * SROW * (int)sizeof(__half);   // 69632 B
    cudaFuncSetAttribute(k_gemm_hmma<float>,
                         cudaFuncAttributeMaxDynamicSharedMemorySize, smem_gemm);
    cudaFuncSetAttribute(k_gemm_hmma<__half>,
                         cudaFuncAttributeMaxDynamicSharedMemorySize, smem_gemm);

    static cudaStream_t s2 = nullptr;
    static cudaEvent_t evFork = nullptr, evJoin = nullptr;
    if (s2 == nullptr) {
        cudaStreamCreateWithFlags(&s2, cudaStreamNonBlocking);
        cudaEventCreateWithFlags(&evFork, cudaEventDisableTiming);
        cudaEventCreateWithFlags(&evJoin, cudaEventDisableTiming);
    }

    const int* srcp = eidx;
    const int* dstp = eidx + E;

    int gb = (N + 127) / 128;
    int ab = (N * 32 + 255) / 256;
    int nb = (N + 1023) / 1024;

    // ---- fork: cvtW + GEMM1 on side stream, CSR chain on main stream ----
    cudaEventRecord(evFork, 0);
    cudaStreamWaitEvent(s2, evFork, 0);
    k_cvtW<<<(DIMF * DIMF + 255) / 256, 256, 0, s2>>>(W1, W2, pW1h, pW2h);
    k_gemm_hmma<float><<<gb, 256, smem_gemm, s2>>>(x, pW1h, pq8, pqs, N);
    cudaEventRecord(evJoin, s2);

    // main stream: CSR build
    k_zero_int<<<(N + 255) / 256, 256>>>(pdeg, N);
    k_hist<<<(E + 255) / 256, 256>>>(dstp, E, pdeg);
    k_scan1<<<nb, 256>>>(pdeg, prow, pbs, pdinv, N);
    k_scan2<<<1, 128>>>(pbs, nb);
    k_scan3<<<nb, 1024>>>(prow, pbs, pdeg, N, E);
    k_scatter<<<(E + 255) / 256, 256>>>(srcp, dstp, E, prow, pdeg, pdinv, pedge);

    // join: agg1 needs GEMM1 output + CSR
    cudaStreamWaitEvent(0, evJoin, 0);
    k_agg<<<ab, 256>>>(pq8, pqs, prow, pedge, pdinv, b1, pb16, N);

    // layer 2 + fused agg/FC/log_softmax
    k_gemm_hmma<__half><<<gb, 256, smem_gemm>>>(pb16, pW2h, pq8, pqs, N);
    k_agg_fc<<<(N + 7) / 8, 256>>>(pq8, pqs, prow, pedge, pdinv, b2, Wfc, bfc, out, N);
}

// round 12
// speedup vs baseline: 1.0716x; 1.0716x over previous
#include <cuda_runtime.h>
#include <cuda_fp16.h>
#include <math.h>

#define NMAX 100000
#define EMAX 3200000
#define DIMF 128
#define SROW (DIMF + 8)   // padded smem row (halves)

// ---------------- scratch ----------------------------------------------------
__device__ __align__(16) __half g_h16[(size_t)NMAX * DIMF];  // GEMM out (gathered)
__device__ __align__(16) __half g_b16[(size_t)NMAX * DIMF];  // agg1 out (GEMM2 in)
__device__ __align__(16) __half g_W1h[DIMF * DIMF];
__device__ __align__(16) __half g_W2h[DIMF * DIMF];
__device__ __align__(16) int    g_deg[NMAX];
__device__ __align__(16) float  g_dinv[NMAX];
__device__ __align__(16) int    g_rowptr[NMAX + 1];
__device__ __align__(16) int    g_bsums[512];
__device__ __align__(16) unsigned long long g_edge[EMAX];    // {ws_bits:32 | col:32}

// ---------------- mma / ldmatrix helpers --------------------------------------
__device__ __forceinline__ unsigned su32(const void* p) {
    return (unsigned)__cvta_generic_to_shared(p);
}
__device__ __forceinline__ void ldsm4(unsigned& r0, unsigned& r1, unsigned& r2,
                                      unsigned& r3, unsigned addr) {
    asm volatile("ldmatrix.sync.aligned.m8n8.x4.shared.b16 {%0,%1,%2,%3}, [%4];"
                 : "=r"(r0), "=r"(r1), "=r"(r2), "=r"(r3) : "r"(addr));
}
__device__ __forceinline__ void ldsm4t(unsigned& r0, unsigned& r1, unsigned& r2,
                                       unsigned& r3, unsigned addr) {
    asm volatile("ldmatrix.sync.aligned.m8n8.x4.trans.shared.b16 {%0,%1,%2,%3}, [%4];"
                 : "=r"(r0), "=r"(r1), "=r"(r2), "=r"(r3) : "r"(addr));
}
__device__ __forceinline__ void mma16816(float* d, unsigned a0, unsigned a1,
                                         unsigned a2, unsigned a3,
                                         unsigned b0, unsigned b1) {
    asm volatile("mma.sync.aligned.m16n8k16.row.col.f32.f16.f16.f32 "
                 "{%0,%1,%2,%3},{%4,%5,%6,%7},{%8,%9},{%0,%1,%2,%3};"
                 : "+f"(d[0]), "+f"(d[1]), "+f"(d[2]), "+f"(d[3])
                 : "r"(a0), "r"(a1), "r"(a2), "r"(a3), "r"(b0), "r"(b1));
}

// ---------------- CSR build ----------------------------------------------------
__global__ void k_zero_int(int* __restrict__ p, int n) {
    int i = blockIdx.x * blockDim.x + threadIdx.x;
    if (i < n) p[i] = 0;
}
__global__ void k_hist(const int* __restrict__ dst, int E, int* __restrict__ deg) {
    int e = blockIdx.x * blockDim.x + threadIdx.x;
    if (e < E) atomicAdd(&deg[dst[e]], 1);
}
__global__ void k_scan1(const int* __restrict__ in, int* __restrict__ out,
                        int* __restrict__ bsums, float* __restrict__ dinv, int n) {
    __shared__ int wsum[8];
    int tid  = threadIdx.x;
    int base = blockIdx.x * 1024 + tid * 4;
    int v0 = 0, v1 = 0, v2 = 0, v3 = 0;
    if (base + 0 < n) v0 = in[base + 0];
    if (base + 1 < n) v1 = in[base + 1];
    if (base + 2 < n) v2 = in[base + 2];
    if (base + 3 < n) v3 = in[base + 3];
    if (base + 0 < n) dinv[base + 0] = rsqrtf((float)(v0 + 1));
    if (base + 1 < n) dinv[base + 1] = rsqrtf((float)(v1 + 1));
    if (base + 2 < n) dinv[base + 2] = rsqrtf((float)(v2 + 1));
    if (base + 3 < n) dinv[base + 3] = rsqrtf((float)(v3 + 1));
    int s = v0 + v1 + v2 + v3;
    int lane = tid & 31, wid = tid >> 5;
    int inc = s;
    #pragma unroll
    for (int o = 1; o < 32; o <<= 1) {
        int t = __shfl_up_sync(0xffffffffu, inc, o);
        if (lane >= o) inc += t;
    }
    if (lane == 31) wsum[wid] = inc;
    __syncthreads();
    if (tid == 0) {
        int run = 0;
        #pragma unroll
        for (int i = 0; i < 8; i++) { int t = wsum[i]; wsum[i] = run; run += t; }
        bsums[blockIdx.x] = run;
    }
    __syncthreads();
    int ex = wsum[wid] + inc - s;
    if (base + 0 < n) out[base + 0] = ex;
    if (base + 1 < n) out[base + 1] = ex + v0;
    if (base + 2 < n) out[base + 2] = ex + v0 + v1;
    if (base + 3 < n) out[base + 3] = ex + v0 + v1 + v2;
}
__global__ void k_scan2(int* __restrict__ bsums, int nb) {
    __shared__ int wsum[4];
    int tid = threadIdx.x;
    int v = (tid < nb) ? bsums[tid] : 0;
    int lane = tid & 31, wid = tid >> 5;
    int inc = v;
    #pragma unroll
    for (int o = 1; o < 32; o <<= 1) {
        int t = __shfl_up_sync(0xffffffffu, inc, o);
        if (lane >= o) inc += t;
    }
    if (lane == 31) wsum[wid] = inc;
    __syncthreads();
    if (tid == 0) {
        int run = 0;
        #pragma unroll
        for (int i = 0; i < 4; i++) { int t = wsum[i]; wsum[i] = run; run += t; }
    }
    __syncthreads();
    if (tid < nb) bsums[tid] = wsum[wid] + inc - v;
}
__global__ void k_scan3(int* __restrict__ rowptr, const int* __restrict__ bsums,
                        int* __restrict__ fill, int n, int E) {
    int i = blockIdx.x * 1024 + threadIdx.x;
    if (i < n) { rowptr[i] += bsums[blockIdx.x]; fill[i] = 0; }
    if (i == 0) rowptr[n] = E;
}
__global__ void k_scatter(const int* __restrict__ srcp, const int* __restrict__ dstp,
                          int E, const int* __restrict__ rowptr, int* __restrict__ fill,
                          const float* __restrict__ dinv,
                          unsigned long long* __restrict__ edge) {
    int e = blockIdx.x * blockDim.x + threadIdx.x;
    if (e >= E) return;
    int s = srcp[e];
    int d = dstp[e];
    int pos = rowptr[d] + atomicAdd(&fill[d], 1);
    unsigned long long w = (unsigned long long)__float_as_uint(dinv[s]);
    edge[pos] = (w << 32) | (unsigned int)s;
}

// ---------------- weight convert ------------------------------------------------
__global__ void k_cvtW(const float* __restrict__ W1, const float* __restrict__ W2,
                       __half* __restrict__ W1h, __half* __restrict__ W2h) {
    int i = blockIdx.x * blockDim.x + threadIdx.x;
    if (i < DIMF * DIMF) {
        W1h[i] = __float2half(W1[i]);
        W2h[i] = __float2half(W2[i]);
    }
}

// ---------------- HMMA GEMM: Y[nrows,128] = X[nrows,128] @ W[128,128] -----------
__device__ __forceinline__ void ldrows(__half (*As)[SROW], const float* X,
                                       int rowbase, int rows, int tid) {
    for (int i = tid; i < rows * 16; i += 256) {
        int r = i >> 4, c8 = (i & 15) * 8;
        const float4* p = (const float4*)(X + (size_t)(rowbase + r) * DIMF + c8);
        float4 f0 = p[0], f1 = p[1];
        __half2 h0 = __floats2half2_rn(f0.x, f0.y), h1 = __floats2half2_rn(f0.z, f0.w);
        __half2 h2 = __floats2half2_rn(f1.x, f1.y), h3 = __floats2half2_rn(f1.z, f1.w);
        uint4 u;
        u.x = *(unsigned*)&h0; u.y = *(unsigned*)&h1;
        u.z = *(unsigned*)&h2; u.w = *(unsigned*)&h3;
        *(uint4*)&As[r][c8] = u;
    }
}
__device__ __forceinline__ void ldrows(__half (*As)[SROW], const __half* X,
                                       int rowbase, int rows, int tid) {
    for (int i = tid; i < rows * 16; i += 256) {
        int r = i >> 4, c8 = (i & 15) * 8;
        *(uint4*)&As[r][c8] = *(const uint4*)(X + (size_t)(rowbase + r) * DIMF + c8);
    }
}

template <typename TIN>
__global__ void k_gemm_hmma(const TIN* __restrict__ X, const __half* __restrict__ Wh,
                            __half* __restrict__ Y, int nrows) {
    extern __shared__ __half smemh[];
    __half (*As)[SROW] = (__half(*)[SROW])smemh;
    __half (*Bs)[SROW] = (__half(*)[SROW])(smemh + 128 * SROW);

    int tid = threadIdx.x;
    int rowbase = blockIdx.x * 128;
    int rows = nrows - rowbase; if (rows > 128) rows = 128;

    #pragma unroll 4
    for (int i = tid; i < 128 * 16; i += 256) {
        int r = i >> 4, c8 = (i & 15) * 8;
        *(uint4*)&Bs[r][c8] = *(const uint4*)(Wh + r * DIMF + c8);
    }
    ldrows(As, X, rowbase, rows, tid);
    __syncthreads();

    int warp = tid >> 5, lane = tid & 31;
    int m0 = warp * 16;
    float acc[16][4];
    #pragma unroll
    for (int i = 0; i < 16; i++)
        #pragma unroll
        for (int j = 0; j < 4; j++) acc[i][j] = 0.f;

    unsigned a_addr = su32(&As[m0 + (lane & 15)][(lane >> 4) * 8]);
    unsigned b_addr = su32(&Bs[lane & 15][(lane >> 4) * 8]);

    #pragma unroll
    for (int ks = 0; ks < 8; ks++) {
        unsigned a0, a1, a2, a3;
        ldsm4(a0, a1, a2, a3, a_addr + ks * 16 * 2);
        #pragma unroll
        for (int pr = 0; pr < 8; pr++) {
            unsigned b0, b1, b2, b3;
            ldsm4t(b0, b1, b2, b3, b_addr + ks * 16 * (SROW * 2) + pr * 16 * 2);
            mma16816(acc[2 * pr + 0], a0, a1, a2, a3, b0, b1);
            mma16816(acc[2 * pr + 1], a0, a1, a2, a3, b2, b3);
        }
    }

    int orow = lane >> 2, ocol = (lane & 3) * 2;
    int r0 = m0 + orow, r1 = r0 + 8;
    bool g0 = (r0 < rows), g1 = (r1 < rows);
    #pragma unroll
    for (int nb = 0; nb < 16; nb++) {
        if (g0) {
            __half2 v = __floats2half2_rn(acc[nb][0], acc[nb][1]);
            *(__half2*)(Y + (size_t)(rowbase + r0) * DIMF + nb * 8 + ocol) = v;
        }
        if (g1) {
            __half2 v = __floats2half2_rn(acc[nb][2], acc[nb][3]);
            *(__half2*)(Y + (size_t)(rowbase + r1) * DIMF + nb * 8 + ocol) = v;
        }
    }
}

// ---------------- agg core: half-warp edge pairing, LDG.128 gathers ------------
// Lanes split: ep = lane>>4 selects edge parity, cl = lane&15 selects 8-dim chunk.
// Each lane accumulates 8 fp32 dims [cl*8, cl*8+8) over its half's edges; a final
// shfl_xor(16) merges the two halves. Per edge: 16 LDG.128 (vs 32 LDG.64 before).
__device__ __forceinline__ void agg_pair(const uint4 q, const float w, float acc[8]) {
    float2 a0 = __half22float2(*(__half2*)&q.x);
    float2 a1 = __half22float2(*(__half2*)&q.y);
    float2 a2 = __half22float2(*(__half2*)&q.z);
    float2 a3 = __half22float2(*(__half2*)&q.w);
    acc[0] = fmaf(w, a0.x, acc[0]); acc[1] = fmaf(w, a0.y, acc[1]);
    acc[2] = fmaf(w, a1.x, acc[2]); acc[3] = fmaf(w, a1.y, acc[3]);
    acc[4] = fmaf(w, a2.x, acc[4]); acc[5] = fmaf(w, a2.y, acc[5]);
    acc[6] = fmaf(w, a3.x, acc[6]); acc[7] = fmaf(w, a3.y, acc[7]);
}

__device__ __forceinline__ void agg_row(const __half* __restrict__ h16,
                                        const unsigned long long* __restrict__ edge,
                                        const float* __restrict__ dinv,
                                        const float* __restrict__ bias,
                                        int v, int e0, int e1, int lane,
                                        float acc[8]) {
    const uint4* h4 = (const uint4*)h16;   // 16 uint4 per 128-dim fp16 row
    int ep = lane >> 4, cl = lane & 15;
    #pragma unroll
    for (int i = 0; i < 8; i++) acc[i] = 0.f;

    int e = e0;
    // 4 pairs = 8 edges per batch; MLP = 4 outstanding LDG.128 per lane
    for (; e + 8 <= e1; e += 8) {
        unsigned long long p[4];
        uint4 q[4];
        #pragma unroll
        for (int j = 0; j < 4; j++) p[j] = __ldg(edge + e + 2 * j + ep);
        #pragma unroll
        for (int j = 0; j < 4; j++)
            q[j] = __ldg(h4 + (size_t)(unsigned)p[j] * 16 + cl);
        #pragma unroll
        for (int j = 0; j < 4; j++)
            agg_pair(q[j], __uint_as_float((unsigned)(p[j] >> 32)), acc);
    }
    // pair tail
    for (; e + 2 <= e1; e += 2) {
        unsigned long long p = __ldg(edge + e + ep);
        uint4 q = __ldg(h4 + (size_t)(unsigned)p * 16 + cl);
        agg_pair(q, __uint_as_float((unsigned)(p >> 32)), acc);
    }
    // single leftover edge: ep==0 half only
    if (e < e1 && ep == 0) {
        unsigned long long p = __ldg(edge + e);
        uint4 q = __ldg(h4 + (size_t)(unsigned)p * 16 + cl);
        agg_pair(q, __uint_as_float((unsigned)(p >> 32)), acc);
    }

    // merge edge-parity halves (lane i <-> i+16 hold same dims)
    #pragma unroll
    for (int i = 0; i < 8; i++)
        acc[i] += __shfl_xor_sync(0xffffffffu, acc[i], 16);

    // self-loop + bias + relu (all lanes; halves now duplicate)
    float dv = dinv[v];
    float sw = dv * dv;
    uint4 qs = __ldg(h4 + (size_t)v * 16 + cl);
    float2 s0 = __half22float2(*(__half2*)&qs.x);
    float2 s1 = __half22float2(*(__half2*)&qs.y);
    float2 s2 = __half22float2(*(__half2*)&qs.z);
    float2 s3 = __half22float2(*(__half2*)&qs.w);
    float4 b0 = __ldg((const float4*)bias + cl * 2 + 0);
    float4 b1 = __ldg((const float4*)bias + cl * 2 + 1);
    acc[0] = fmaxf(fmaf(dv, acc[0], fmaf(sw, s0.x, b0.x)), 0.f);
    acc[1] = fmaxf(fmaf(dv, acc[1], fmaf(sw, s0.y, b0.y)), 0.f);
    acc[2] = fmaxf(fmaf(dv, acc[2], fmaf(sw, s1.x, b0.z)), 0.f);
    acc[3] = fmaxf(fmaf(dv, acc[3], fmaf(sw, s1.y, b0.w)), 0.f);
    acc[4] = fmaxf(fmaf(dv, acc[4], fmaf(sw, s2.x, b1.x)), 0.f);
    acc[5] = fmaxf(fmaf(dv, acc[5], fmaf(sw, s2.y, b1.y)), 0.f);
    acc[6] = fmaxf(fmaf(dv, acc[6], fmaf(sw, s3.x, b1.z)), 0.f);
    acc[7] = fmaxf(fmaf(dv, acc[7], fmaf(sw, s3.y, b1.w)), 0.f);
}

// layer-1 aggregation: fp16 out (GEMM2 input)
__global__ void k_agg(const __half* __restrict__ h16, const int* __restrict__ rowptr,
                      const unsigned long long* __restrict__ edge,
                      const float* __restrict__ dinv, const float* __restrict__ bias,
                      __half* __restrict__ out, int N) {
    int v = (blockIdx.x * blockDim.x + threadIdx.x) >> 5;
    int lane = threadIdx.x & 31;
    if (v >= N) return;
    int e0 = rowptr[v], e1 = rowptr[v + 1];
    float acc[8];
    agg_row(h16, edge, dinv, bias, v, e0, e1, lane, acc);
    if (lane < 16) {
        __half2 h0 = __floats2half2_rn(acc[0], acc[1]);
        __half2 h1 = __floats2half2_rn(acc[2], acc[3]);
        __half2 h2 = __floats2half2_rn(acc[4], acc[5]);
        __half2 h3 = __floats2half2_rn(acc[6], acc[7]);
        uint4 u;
        u.x = *(unsigned*)&h0; u.y = *(unsigned*)&h1;
        u.z = *(unsigned*)&h2; u.w = *(unsigned*)&h3;
        ((uint4*)(out + (size_t)v * DIMF))[lane] = u;
    }
}

// layer-2 aggregation fused with FC(128->40) + log_softmax
__global__ void k_agg_fc(const __half* __restrict__ h16, const int* __restrict__ rowptr,
                         const unsigned long long* __restrict__ edge,
                         const float* __restrict__ dinv, const float* __restrict__ bias,
                         const float* __restrict__ Wfc, const float* __restrict__ bfc,
                         float* __restrict__ out, int N) {
    __shared__ __align__(16) float sh[8][DIMF];
    int w = threadIdx.x >> 5;
    int lane = threadIdx.x & 31;
    int v = blockIdx.x * 8 + w;
    if (v >= N) return;

    int e0 = rowptr[v], e1 = rowptr[v + 1];
    float acc[8];
    agg_row(h16, edge, dinv, bias, v, e0, e1, lane, acc);
    if (lane < 16) {
        int cl = lane;
        ((float4*)&sh[w][0])[cl * 2 + 0] = make_float4(acc[0], acc[1], acc[2], acc[3]);
        ((float4*)&sh[w][0])[cl * 2 + 1] = make_float4(acc[4], acc[5], acc[6], acc[7]);
    }
    __syncwarp();

    float acc0 = 0.f, acc1 = 0.f;
    bool hi = (lane < 8);
    #pragma unroll 4
    for (int k4 = 0; k4 < 32; k4++) {
        float4 xv = ((const float4*)&sh[w][0])[k4];
        int k = k4 * 4;
        acc0 = fmaf(xv.x, __ldg(Wfc + (k + 0) * 40 + lane), acc0);
        acc0 = fmaf(xv.y, __ldg(Wfc + (k + 1) * 40 + lane), acc0);
        acc0 = fmaf(xv.z, __ldg(Wfc + (k + 2) * 40 + lane), acc0);
        acc0 = fmaf(xv.w, __ldg(Wfc + (k + 3) * 40 + lane), acc0);
        if (hi) {
            acc1 = fmaf(xv.x, __ldg(Wfc + (k + 0) * 40 + 32 + lane), acc1);
            acc1 = fmaf(xv.y, __ldg(Wfc + (k + 1) * 40 + 32 + lane), acc1);
            acc1 = fmaf(xv.z, __ldg(Wfc + (k + 2) * 40 + 32 + lane), acc1);
            acc1 = fmaf(xv.w, __ldg(Wfc + (k + 3) * 40 + 32 + lane), acc1);
        }
    }
    acc0 += __ldg(bfc + lane);
    if (hi) acc1 += __ldg(bfc + 32 + lane);

    float m = hi ? fmaxf(acc0, acc1) : acc0;
    #pragma unroll
    for (int o2 = 16; o2; o2 >>= 1) m = fmaxf(m, __shfl_xor_sync(0xffffffffu, m, o2));
    float s = expf(acc0 - m) + (hi ? expf(acc1 - m) : 0.f);
    #pragma unroll
    for (int o2 = 16; o2; o2 >>= 1) s += __shfl_xor_sync(0xffffffffu, s, o2);
    float lse = logf(s) + m;

    out[(size_t)v * 40 + lane] = acc0 - lse;
    if (hi) out[(size_t)v * 40 + 32 + lane] = acc1 - lse;
}

// ---------------- host launcher ----------------------------------------------
extern "C" void kernel_launch(void* const* d_in, const int* in_sizes, int n_in,
                              void* d_out, int out_size) {
    const float* x    = (const float*)d_in[0];
    const float* W1   = (const float*)d_in[1];
    const float* b1   = (const float*)d_in[2];
    const float* W2   = (const float*)d_in[3];
    const float* b2   = (const float*)d_in[4];
    const float* Wfc  = (const float*)d_in[5];
    const float* bfc  = (const float*)d_in[6];
    const int*   eidx = (const int*)d_in[7];
    float* out = (float*)d_out;

    int N = in_sizes[0] / DIMF;
    int E = in_sizes[7] / 2;
    if (N > NMAX) N = NMAX;
    if (E > EMAX) E = EMAX;

    __half *ph16, *pb16, *pW1h, *pW2h;
    float* pdinv;
    int *pdeg, *prow, *pbs;
    unsigned long long* pedge;
    cudaGetSymbolAddress((void**)&ph16,  g_h16);
    cudaGetSymbolAddress((void**)&pb16,  g_b16);
    cudaGetSymbolAddress((void**)&pW1h,  g_W1h);
    cudaGetSymbolAddress((void**)&pW2h,  g_W2h);
    cudaGetSymbolAddress((void**)&pdeg,  g_deg);
    cudaGetSymbolAddress((void**)&pdinv, g_dinv);
    cudaGetSymbolAddress((void**)&prow,  g_rowptr);
    cudaGetSymbolAddress((void**)&pbs,   g_bsums);
    cudaGetSymbolAddress((void**)&pedge, g_edge);

    int smem_gemm = 2 * 128 * SROW * (int)sizeof(__half);   // 69632 B
    cudaFuncSetAttribute(k_gemm_hmma<float>,
                         cudaFuncAttributeMaxDynamicSharedMemorySize, smem_gemm);
    cudaFuncSetAttribute(k_gemm_hmma<__half>,
                         cudaFuncAttributeMaxDynamicSharedMemorySize, smem_gemm);

    static cudaStream_t s2 = nullptr;
    static cudaEvent_t evFork = nullptr, evJoin = nullptr;
    if (s2 == nullptr) {
        cudaStreamCreateWithFlags(&s2, cudaStreamNonBlocking);
        cudaEventCreateWithFlags(&evFork, cudaEventDisableTiming);
        cudaEventCreateWithFlags(&evJoin, cudaEventDisableTiming);
    }

    const int* srcp = eidx;
    const int* dstp = eidx + E;

    int gb = (N + 127) / 128;
    int ab = (N * 32 + 255) / 256;
    int nb = (N + 1023) / 1024;

    // ---- fork: cvtW + GEMM1 on side stream, CSR chain on main stream ----
    cudaEventRecord(evFork, 0);
    cudaStreamWaitEvent(s2, evFork, 0);
    k_cvtW<<<(DIMF * DIMF + 255) / 256, 256, 0, s2>>>(W1, W2, pW1h, pW2h);
    k_gemm_hmma<float><<<gb, 256, smem_gemm, s2>>>(x, pW1h, ph16, N);
    cudaEventRecord(evJoin, s2);

    // main stream: CSR build
    k_zero_int<<<(N + 255) / 256, 256>>>(pdeg, N);
    k_hist<<<(E + 255) / 256, 256>>>(dstp, E, pdeg);
    k_scan1<<<nb, 256>>>(pdeg, prow, pbs, pdinv, N);
    k_scan2<<<1, 128>>>(pbs, nb);
    k_scan3<<<nb, 1024>>>(prow, pbs, pdeg, N, E);
    k_scatter<<<(E + 255) / 256, 256>>>(srcp, dstp, E, prow, pdeg, pdinv, pedge);

    // join: agg1 needs GEMM1 output + CSR
    cudaStreamWaitEvent(0, evJoin, 0);
    k_agg<<<ab, 256>>>(ph16, prow, pedge, pdinv, b1, pb16, N);

    // layer 2 + fused agg/FC/log_softmax
    k_gemm_hmma<__half><<<gb, 256, smem_gemm>>>(pb16, pW2h, ph16, N);
    k_agg_fc<<<(N + 7) / 8, 256>>>(ph16, prow, pedge, pdinv, b2, Wfc, bfc, out, N);
}

// round 13
// speedup vs baseline: 1.0723x; 1.0006x over previous
#include <cuda_runtime.h>
#include <cuda_fp16.h>
#include <math.h>

#define NMAX 100000
#define EMAX 3200000
#define DIMF 128
#define SROW (DIMF + 8)   // padded smem row (halves)

// ---------------- scratch ----------------------------------------------------
__device__ __align__(16) __half g_h16[(size_t)NMAX * DIMF];  // GEMM out (gathered)
__device__ __align__(16) __half g_b16[(size_t)NMAX * DIMF];  // agg1 out (GEMM2 in)
__device__ __align__(16) __half g_W1h[DIMF * DIMF];
__device__ __align__(16) __half g_W2h[DIMF * DIMF];
__device__ __align__(16) int    g_deg[NMAX];
__device__ __align__(16) float  g_dinv[NMAX];
__device__ __align__(16) int    g_rowptr[NMAX + 1];
__device__ __align__(16) int    g_bsums[512];
__device__ __align__(16) unsigned long long g_edge[EMAX];    // {ws_bits:32 | col:32}

// ---------------- mma / ldmatrix helpers --------------------------------------
__device__ __forceinline__ unsigned su32(const void* p) {
    return (unsigned)__cvta_generic_to_shared(p);
}
__device__ __forceinline__ void ldsm4(unsigned& r0, unsigned& r1, unsigned& r2,
                                      unsigned& r3, unsigned addr) {
    asm volatile("ldmatrix.sync.aligned.m8n8.x4.shared.b16 {%0,%1,%2,%3}, [%4];"
                 : "=r"(r0), "=r"(r1), "=r"(r2), "=r"(r3) : "r"(addr));
}
__device__ __forceinline__ void ldsm4t(unsigned& r0, unsigned& r1, unsigned& r2,
                                       unsigned& r3, unsigned addr) {
    asm volatile("ldmatrix.sync.aligned.m8n8.x4.trans.shared.b16 {%0,%1,%2,%3}, [%4];"
                 : "=r"(r0), "=r"(r1), "=r"(r2), "=r"(r3) : "r"(addr));
}
__device__ __forceinline__ void mma16816(float* d, unsigned a0, unsigned a1,
                                         unsigned a2, unsigned a3,
                                         unsigned b0, unsigned b1) {
    asm volatile("mma.sync.aligned.m16n8k16.row.col.f32.f16.f16.f32 "
                 "{%0,%1,%2,%3},{%4,%5,%6,%7},{%8,%9},{%0,%1,%2,%3};"
                 : "+f"(d[0]), "+f"(d[1]), "+f"(d[2]), "+f"(d[3])
                 : "r"(a0), "r"(a1), "r"(a2), "r"(a3), "r"(b0), "r"(b1));
}

// ---------------- CSR build ----------------------------------------------------
__global__ void k_hist(const int* __restrict__ dst, int E, int* __restrict__ deg) {
    int e = blockIdx.x * blockDim.x + threadIdx.x;
    if (e < E) atomicAdd(&deg[dst[e]], 1);
}
__global__ void k_scan1(const int* __restrict__ in, int* __restrict__ out,
                        int* __restrict__ bsums, float* __restrict__ dinv, int n) {
    __shared__ int wsum[8];
    int tid  = threadIdx.x;
    int base = blockIdx.x * 1024 + tid * 4;
    int v0 = 0, v1 = 0, v2 = 0, v3 = 0;
    if (base + 0 < n) v0 = in[base + 0];
    if (base + 1 < n) v1 = in[base + 1];
    if (base + 2 < n) v2 = in[base + 2];
    if (base + 3 < n) v3 = in[base + 3];
    if (base + 0 < n) dinv[base + 0] = rsqrtf((float)(v0 + 1));
    if (base + 1 < n) dinv[base + 1] = rsqrtf((float)(v1 + 1));
    if (base + 2 < n) dinv[base + 2] = rsqrtf((float)(v2 + 1));
    if (base + 3 < n) dinv[base + 3] = rsqrtf((float)(v3 + 1));
    int s = v0 + v1 + v2 + v3;
    int lane = tid & 31, wid = tid >> 5;
    int inc = s;
    #pragma unroll
    for (int o = 1; o < 32; o <<= 1) {
        int t = __shfl_up_sync(0xffffffffu, inc, o);
        if (lane >= o) inc += t;
    }
    if (lane == 31) wsum[wid] = inc;
    __syncthreads();
    if (tid == 0) {
        int run = 0;
        #pragma unroll
        for (int i = 0; i < 8; i++) { int t = wsum[i]; wsum[i] = run; run += t; }
        bsums[blockIdx.x] = run;
    }
    __syncthreads();
    int ex = wsum[wid] + inc - s;
    if (base + 0 < n) out[base + 0] = ex;
    if (base + 1 < n) out[base + 1] = ex + v0;
    if (base + 2 < n) out[base + 2] = ex + v0 + v1;
    if (base + 3 < n) out[base + 3] = ex + v0 + v1 + v2;
}
__global__ void k_scan2(int* __restrict__ bsums, int nb) {
    __shared__ int wsum[4];
    int tid = threadIdx.x;
    int v = (tid < nb) ? bsums[tid] : 0;
    int lane = tid & 31, wid = tid >> 5;
    int inc = v;
    #pragma unroll
    for (int o = 1; o < 32; o <<= 1) {
        int t = __shfl_up_sync(0xffffffffu, inc, o);
        if (lane >= o) inc += t;
    }
    if (lane == 31) wsum[wid] = inc;
    __syncthreads();
    if (tid == 0) {
        int run = 0;
        #pragma unroll
        for (int i = 0; i < 4; i++) { int t = wsum[i]; wsum[i] = run; run += t; }
    }
    __syncthreads();
    if (tid < nb) bsums[tid] = wsum[wid] + inc - v;
}
__global__ void k_scan3(int* __restrict__ rowptr, const int* __restrict__ bsums,
                        int* __restrict__ fill, int n, int E) {
    int i = blockIdx.x * 1024 + threadIdx.x;
    if (i < n) { rowptr[i] += bsums[blockIdx.x]; fill[i] = 0; }
    if (i == 0) rowptr[n] = E;
}
__global__ void k_scatter(const int* __restrict__ srcp, const int* __restrict__ dstp,
                          int E, const int* __restrict__ rowptr, int* __restrict__ fill,
                          const float* __restrict__ dinv,
                          unsigned long long* __restrict__ edge) {
    int e = blockIdx.x * blockDim.x + threadIdx.x;
    if (e >= E) return;
    int s = srcp[e];
    int d = dstp[e];
    int pos = rowptr[d] + atomicAdd(&fill[d], 1);
    unsigned long long w = (unsigned long long)__float_as_uint(dinv[s]);
    edge[pos] = (w << 32) | (unsigned int)s;
}

// ---------------- weight convert ------------------------------------------------
__global__ void k_cvtW(const float* __restrict__ W1, const float* __restrict__ W2,
                       __half* __restrict__ W1h, __half* __restrict__ W2h) {
    int i = blockIdx.x * blockDim.x + threadIdx.x;
    if (i < DIMF * DIMF) {
        W1h[i] = __float2half(W1[i]);
        W2h[i] = __float2half(W2[i]);
    }
}

// ---------------- HMMA GEMM: Y[nrows,128] = X[nrows,128] @ W[128,128] -----------
__device__ __forceinline__ void ldrows(__half (*As)[SROW], const float* X,
                                       int rowbase, int rows, int tid) {
    for (int i = tid; i < rows * 16; i += 256) {
        int r = i >> 4, c8 = (i & 15) * 8;
        const float4* p = (const float4*)(X + (size_t)(rowbase + r) * DIMF + c8);
        float4 f0 = p[0], f1 = p[1];
        __half2 h0 = __floats2half2_rn(f0.x, f0.y), h1 = __floats2half2_rn(f0.z, f0.w);
        __half2 h2 = __floats2half2_rn(f1.x, f1.y), h3 = __floats2half2_rn(f1.z, f1.w);
        uint4 u;
        u.x = *(unsigned*)&h0; u.y = *(unsigned*)&h1;
        u.z = *(unsigned*)&h2; u.w = *(unsigned*)&h3;
        *(uint4*)&As[r][c8] = u;
    }
}
__device__ __forceinline__ void ldrows(__half (*As)[SROW], const __half* X,
                                       int rowbase, int rows, int tid) {
    for (int i = tid; i < rows * 16; i += 256) {
        int r = i >> 4, c8 = (i & 15) * 8;
        *(uint4*)&As[r][c8] = *(const uint4*)(X + (size_t)(rowbase + r) * DIMF + c8);
    }
}

template <typename TIN>
__global__ void k_gemm_hmma(const TIN* __restrict__ X, const __half* __restrict__ Wh,
                            __half* __restrict__ Y, int nrows) {
    extern __shared__ __half smemh[];
    __half (*As)[SROW] = (__half(*)[SROW])smemh;
    __half (*Bs)[SROW] = (__half(*)[SROW])(smemh + 128 * SROW);

    int tid = threadIdx.x;
    int rowbase = blockIdx.x * 128;
    int rows = nrows - rowbase; if (rows > 128) rows = 128;

    #pragma unroll 4
    for (int i = tid; i < 128 * 16; i += 256) {
        int r = i >> 4, c8 = (i & 15) * 8;
        *(uint4*)&Bs[r][c8] = *(const uint4*)(Wh + r * DIMF + c8);
    }
    ldrows(As, X, rowbase, rows, tid);
    __syncthreads();

    int warp = tid >> 5, lane = tid & 31;
    int m0 = warp * 16;
    float acc[16][4];
    #pragma unroll
    for (int i = 0; i < 16; i++)
        #pragma unroll
        for (int j = 0; j < 4; j++) acc[i][j] = 0.f;

    unsigned a_addr = su32(&As[m0 + (lane & 15)][(lane >> 4) * 8]);
    unsigned b_addr = su32(&Bs[lane & 15][(lane >> 4) * 8]);

    #pragma unroll
    for (int ks = 0; ks < 8; ks++) {
        unsigned a0, a1, a2, a3;
        ldsm4(a0, a1, a2, a3, a_addr + ks * 16 * 2);
        #pragma unroll
        for (int pr = 0; pr < 8; pr++) {
            unsigned b0, b1, b2, b3;
            ldsm4t(b0, b1, b2, b3, b_addr + ks * 16 * (SROW * 2) + pr * 16 * 2);
            mma16816(acc[2 * pr + 0], a0, a1, a2, a3, b0, b1);
            mma16816(acc[2 * pr + 1], a0, a1, a2, a3, b2, b3);
        }
    }

    int orow = lane >> 2, ocol = (lane & 3) * 2;
    int r0 = m0 + orow, r1 = r0 + 8;
    bool g0 = (r0 < rows), g1 = (r1 < rows);
    #pragma unroll
    for (int nb = 0; nb < 16; nb++) {
        if (g0) {
            __half2 v = __floats2half2_rn(acc[nb][0], acc[nb][1]);
            *(__half2*)(Y + (size_t)(rowbase + r0) * DIMF + nb * 8 + ocol) = v;
        }
        if (g1) {
            __half2 v = __floats2half2_rn(acc[nb][2], acc[nb][3]);
            *(__half2*)(Y + (size_t)(rowbase + r1) * DIMF + nb * 8 + ocol) = v;
        }
    }
}

// ---------------- agg core: half-warp edge pairing, 16-edge batches ------------
// ep = lane>>4 (edge parity), cl = lane&15 (8-dim chunk). 8 outstanding LDG.128
// row loads per lane per batch (MLP=8).
__device__ __forceinline__ void agg_pair(const uint4 q, const float w, float acc[8]) {
    float2 a0 = __half22float2(*(__half2*)&q.x);
    float2 a1 = __half22float2(*(__half2*)&q.y);
    float2 a2 = __half22float2(*(__half2*)&q.z);
    float2 a3 = __half22float2(*(__half2*)&q.w);
    acc[0] = fmaf(w, a0.x, acc[0]); acc[1] = fmaf(w, a0.y, acc[1]);
    acc[2] = fmaf(w, a1.x, acc[2]); acc[3] = fmaf(w, a1.y, acc[3]);
    acc[4] = fmaf(w, a2.x, acc[4]); acc[5] = fmaf(w, a2.y, acc[5]);
    acc[6] = fmaf(w, a3.x, acc[6]); acc[7] = fmaf(w, a3.y, acc[7]);
}

__device__ __forceinline__ void agg_row(const __half* __restrict__ h16,
                                        const unsigned long long* __restrict__ edge,
                                        const float* __restrict__ dinv,
                                        const float* __restrict__ bias,
                                        int v, int e0, int e1, int lane,
                                        float acc[8]) {
    const uint4* h4 = (const uint4*)h16;   // 16 uint4 per 128-dim fp16 row
    int ep = lane >> 4, cl = lane & 15;
    #pragma unroll
    for (int i = 0; i < 8; i++) acc[i] = 0.f;

    int e = e0;
    // 8 pairs = 16 edges per batch; 8 outstanding LDG.128 per lane
    for (; e + 16 <= e1; e += 16) {
        unsigned long long p[8];
        uint4 q[8];
        #pragma unroll
        for (int j = 0; j < 8; j++) p[j] = __ldg(edge + e + 2 * j + ep);
        #pragma unroll
        for (int j = 0; j < 8; j++)
            q[j] = __ldg(h4 + (size_t)(unsigned)p[j] * 16 + cl);
        #pragma unroll
        for (int j = 0; j < 8; j++)
            agg_pair(q[j], __uint_as_float((unsigned)(p[j] >> 32)), acc);
    }
    // pair tail
    for (; e + 2 <= e1; e += 2) {
        unsigned long long p = __ldg(edge + e + ep);
        uint4 q = __ldg(h4 + (size_t)(unsigned)p * 16 + cl);
        agg_pair(q, __uint_as_float((unsigned)(p >> 32)), acc);
    }
    // single leftover edge: ep==0 half only
    if (e < e1 && ep == 0) {
        unsigned long long p = __ldg(edge + e);
        uint4 q = __ldg(h4 + (size_t)(unsigned)p * 16 + cl);
        agg_pair(q, __uint_as_float((unsigned)(p >> 32)), acc);
    }

    // merge edge-parity halves
    #pragma unroll
    for (int i = 0; i < 8; i++)
        acc[i] += __shfl_xor_sync(0xffffffffu, acc[i], 16);

    // self-loop + bias + relu
    float dv = dinv[v];
    float sw = dv * dv;
    uint4 qs = __ldg(h4 + (size_t)v * 16 + cl);
    float2 s0 = __half22float2(*(__half2*)&qs.x);
    float2 s1 = __half22float2(*(__half2*)&qs.y);
    float2 s2 = __half22float2(*(__half2*)&qs.z);
    float2 s3 = __half22float2(*(__half2*)&qs.w);
    float4 b0 = __ldg((const float4*)bias + cl * 2 + 0);
    float4 b1 = __ldg((const float4*)bias + cl * 2 + 1);
    acc[0] = fmaxf(fmaf(dv, acc[0], fmaf(sw, s0.x, b0.x)), 0.f);
    acc[1] = fmaxf(fmaf(dv, acc[1], fmaf(sw, s0.y, b0.y)), 0.f);
    acc[2] = fmaxf(fmaf(dv, acc[2], fmaf(sw, s1.x, b0.z)), 0.f);
    acc[3] = fmaxf(fmaf(dv, acc[3], fmaf(sw, s1.y, b0.w)), 0.f);
    acc[4] = fmaxf(fmaf(dv, acc[4], fmaf(sw, s2.x, b1.x)), 0.f);
    acc[5] = fmaxf(fmaf(dv, acc[5], fmaf(sw, s2.y, b1.y)), 0.f);
    acc[6] = fmaxf(fmaf(dv, acc[6], fmaf(sw, s3.x, b1.z)), 0.f);
    acc[7] = fmaxf(fmaf(dv, acc[7], fmaf(sw, s3.y, b1.w)), 0.f);
}

// layer-1 aggregation: fp16 out (GEMM2 input)
__global__ void k_agg(const __half* __restrict__ h16, const int* __restrict__ rowptr,
                      const unsigned long long* __restrict__ edge,
                      const float* __restrict__ dinv, const float* __restrict__ bias,
                      __half* __restrict__ out, int N) {
    int v = (blockIdx.x * blockDim.x + threadIdx.x) >> 5;
    int lane = threadIdx.x & 31;
    if (v >= N) return;
    int e0 = rowptr[v], e1 = rowptr[v + 1];
    float acc[8];
    agg_row(h16, edge, dinv, bias, v, e0, e1, lane, acc);
    if (lane < 16) {
        __half2 h0 = __floats2half2_rn(acc[0], acc[1]);
        __half2 h1 = __floats2half2_rn(acc[2], acc[3]);
        __half2 h2 = __floats2half2_rn(acc[4], acc[5]);
        __half2 h3 = __floats2half2_rn(acc[6], acc[7]);
        uint4 u;
        u.x = *(unsigned*)&h0; u.y = *(unsigned*)&h1;
        u.z = *(unsigned*)&h2; u.w = *(unsigned*)&h3;
        ((uint4*)(out + (size_t)v * DIMF))[lane] = u;
    }
}

// layer-2 aggregation fused with FC(128->40) + log_softmax
__global__ void k_agg_fc(const __half* __restrict__ h16, const int* __restrict__ rowptr,
                         const unsigned long long* __restrict__ edge,
                         const float* __restrict__ dinv, const float* __restrict__ bias,
                         const float* __restrict__ Wfc, const float* __restrict__ bfc,
                         float* __restrict__ out, int N) {
    __shared__ __align__(16) float sh[8][DIMF];
    int w = threadIdx.x >> 5;
    int lane = threadIdx.x & 31;
    int v = blockIdx.x * 8 + w;
    if (v >= N) return;

    int e0 = rowptr[v], e1 = rowptr[v + 1];
    float acc[8];
    agg_row(h16, edge, dinv, bias, v, e0, e1, lane, acc);
    if (lane < 16) {
        int cl = lane;
        ((float4*)&sh[w][0])[cl * 2 + 0] = make_float4(acc[0], acc[1], acc[2], acc[3]);
        ((float4*)&sh[w][0])[cl * 2 + 1] = make_float4(acc[4], acc[5], acc[6], acc[7]);
    }
    __syncwarp();

    float acc0 = 0.f, acc1 = 0.f;
    bool hi = (lane < 8);
    #pragma unroll 4
    for (int k4 = 0; k4 < 32; k4++) {
        float4 xv = ((const float4*)&sh[w][0])[k4];
        int k = k4 * 4;
        acc0 = fmaf(xv.x, __ldg(Wfc + (k + 0) * 40 + lane), acc0);
        acc0 = fmaf(xv.y, __ldg(Wfc + (k + 1) * 40 + lane), acc0);
        acc0 = fmaf(xv.z, __ldg(Wfc + (k + 2) * 40 + lane), acc0);
        acc0 = fmaf(xv.w, __ldg(Wfc + (k + 3) * 40 + lane), acc0);
        if (hi) {
            acc1 = fmaf(xv.x, __ldg(Wfc + (k + 0) * 40 + 32 + lane), acc1);
            acc1 = fmaf(xv.y, __ldg(Wfc + (k + 1) * 40 + 32 + lane), acc1);
            acc1 = fmaf(xv.z, __ldg(Wfc + (k + 2) * 40 + 32 + lane), acc1);
            acc1 = fmaf(xv.w, __ldg(Wfc + (k + 3) * 40 + 32 + lane), acc1);
        }
    }
    acc0 += __ldg(bfc + lane);
    if (hi) acc1 += __ldg(bfc + 32 + lane);

    float m = hi ? fmaxf(acc0, acc1) : acc0;
    #pragma unroll
    for (int o2 = 16; o2; o2 >>= 1) m = fmaxf(m, __shfl_xor_sync(0xffffffffu, m, o2));
    float s = expf(acc0 - m) + (hi ? expf(acc1 - m) : 0.f);
    #pragma unroll
    for (int o2 = 16; o2; o2 >>= 1) s += __shfl_xor_sync(0xffffffffu, s, o2);
    float lse = logf(s) + m;

    out[(size_t)v * 40 + lane] = acc0 - lse;
    if (hi) out[(size_t)v * 40 + 32 + lane] = acc1 - lse;
}

// ---------------- host launcher ----------------------------------------------
extern "C" void kernel_launch(void* const* d_in, const int* in_sizes, int n_in,
                              void* d_out, int out_size) {
    const float* x    = (const float*)d_in[0];
    const float* W1   = (const float*)d_in[1];
    const float* b1   = (const float*)d_in[2];
    const float* W2   = (const float*)d_in[3];
    const float* b2   = (const float*)d_in[4];
    const float* Wfc  = (const float*)d_in[5];
    const float* bfc  = (const float*)d_in[6];
    const int*   eidx = (const int*)d_in[7];
    float* out = (float*)d_out;

    int N = in_sizes[0] / DIMF;
    int E = in_sizes[7] / 2;
    if (N > NMAX) N = NMAX;
    if (E > EMAX) E = EMAX;

    __half *ph16, *pb16, *pW1h, *pW2h;
    float* pdinv;
    int *pdeg, *prow, *pbs;
    unsigned long long* pedge;
    cudaGetSymbolAddress((void**)&ph16,  g_h16);
    cudaGetSymbolAddress((void**)&pb16,  g_b16);
    cudaGetSymbolAddress((void**)&pW1h,  g_W1h);
    cudaGetSymbolAddress((void**)&pW2h,  g_W2h);
    cudaGetSymbolAddress((void**)&pdeg,  g_deg);
    cudaGetSymbolAddress((void**)&pdinv, g_dinv);
    cudaGetSymbolAddress((void**)&prow,  g_rowptr);
    cudaGetSymbolAddress((void**)&pbs,   g_bsums);
    cudaGetSymbolAddress((void**)&pedge, g_edge);

    int smem_gemm = 2 * 128 * SROW * (int)sizeof(__half);   // 69632 B
    cudaFuncSetAttribute(k_gemm_hmma<float>,
                         cudaFuncAttributeMaxDynamicSharedMemorySize, smem_gemm);
    cudaFuncSetAttribute(k_gemm_hmma<__half>,
                         cudaFuncAttributeMaxDynamicSharedMemorySize, smem_gemm);

    static cudaStream_t s2 = nullptr;
    static cudaEvent_t evFork = nullptr, evJoin = nullptr;
    if (s2 == nullptr) {
        cudaStreamCreateWithFlags(&s2, cudaStreamNonBlocking);
        cudaEventCreateWithFlags(&evFork, cudaEventDisableTiming);
        cudaEventCreateWithFlags(&evJoin, cudaEventDisableTiming);
    }

    const int* srcp = eidx;
    const int* dstp = eidx + E;

    int gb = (N + 127) / 128;
    int ab = (N * 32 + 255) / 256;
    int nb = (N + 1023) / 1024;

    // ---- fork: cvtW + GEMM1 on side stream, CSR chain on main stream ----
    cudaEventRecord(evFork, 0);
    cudaStreamWaitEvent(s2, evFork, 0);
    k_cvtW<<<(DIMF * DIMF + 255) / 256, 256, 0, s2>>>(W1, W2, pW1h, pW2h);
    k_gemm_hmma<float><<<gb, 256, smem_gemm, s2>>>(x, pW1h, ph16, N);
    cudaEventRecord(evJoin, s2);

    // main stream: CSR build
    cudaMemsetAsync(pdeg, 0, (size_t)N * sizeof(int));
    k_hist<<<(E + 255) / 256, 256>>>(dstp, E, pdeg);
    k_scan1<<<nb, 256>>>(pdeg, prow, pbs, pdinv, N);
    k_scan2<<<1, 128>>>(pbs, nb);
    k_scan3<<<nb, 1024>>>(prow, pbs, pdeg, N, E);
    k_scatter<<<(E + 255) / 256, 256>>>(srcp, dstp, E, prow, pdeg, pdinv, pedge);

    // join: agg1 needs GEMM1 output + CSR
    cudaStreamWaitEvent(0, evJoin, 0);
    k_agg<<<ab, 256>>>(ph16, prow, pedge, pdinv, b1, pb16, N);

    // layer 2 + fused agg/FC/log_softmax
    k_gemm_hmma<__half><<<gb, 256, smem_gemm>>>(pb16, pW2h, ph16, N);
    k_agg_fc<<<(N + 7) / 8, 256>>>(ph16, prow, pedge, pdinv, b2, Wfc, bfc, out, N);
}